// round 2
// baseline (speedup 1.0000x reference)
#include <cuda_runtime.h>
#include <math.h>

#define NTOK   257
#define BATCH  64
#define T_TOK  (BATCH * NTOK)   // 16448
#define DMODEL 1024
#define NHEAD  16
#define HD     64
#define HDIM   4096
#define LN_EPS 1e-5f

// ---------------- scratch (device globals; no allocations allowed) ----------
__device__ float g_xn [(size_t)T_TOK * DMODEL];
__device__ float g_q  [(size_t)T_TOK * DMODEL];
__device__ float g_k  [(size_t)T_TOK * DMODEL];
__device__ float g_v  [(size_t)T_TOK * DMODEL];
__device__ float g_att[(size_t)T_TOK * DMODEL];
__device__ float g_x1 [(size_t)T_TOK * DMODEL];
__device__ float g_h1 [(size_t)T_TOK * HDIM];
__device__ float g_h2 [(size_t)T_TOK * HDIM];

// ---------------- LayerNorm (one row per block, 256 threads) ----------------
template<int W>
__global__ void __launch_bounds__(256) ln_kernel(const float* __restrict__ x,
                                                 const float* __restrict__ g,
                                                 const float* __restrict__ b,
                                                 float* __restrict__ y)
{
    constexpr int V = W / 1024;             // float4s per thread
    __shared__ float red0[8], red1[8];
    __shared__ float stats[2];
    size_t rb = (size_t)blockIdx.x * W;
    const float4* xr = (const float4*)(x + rb);
    float4 vv[V];
    float s = 0.f, s2 = 0.f;
#pragma unroll
    for (int i = 0; i < V; i++) {
        float4 t = xr[threadIdx.x + i * 256];
        vv[i] = t;
        s  += t.x + t.y + t.z + t.w;
        s2 += t.x*t.x + t.y*t.y + t.z*t.z + t.w*t.w;
    }
#pragma unroll
    for (int o = 16; o; o >>= 1) {
        s  += __shfl_xor_sync(0xffffffffu, s,  o);
        s2 += __shfl_xor_sync(0xffffffffu, s2, o);
    }
    if ((threadIdx.x & 31) == 0) { red0[threadIdx.x >> 5] = s; red1[threadIdx.x >> 5] = s2; }
    __syncthreads();
    if (threadIdx.x == 0) {
        float a = 0.f, c = 0.f;
#pragma unroll
        for (int i = 0; i < 8; i++) { a += red0[i]; c += red1[i]; }
        float mu  = a / (float)W;
        float var = c / (float)W - mu * mu;
        stats[0] = mu;
        stats[1] = rsqrtf(var + LN_EPS);
    }
    __syncthreads();
    float mu = stats[0], inv = stats[1];
    float4* yr = (float4*)(y + rb);
    const float4* g4 = (const float4*)g;
    const float4* b4 = (const float4*)b;
#pragma unroll
    for (int i = 0; i < V; i++) {
        int c = threadIdx.x + i * 256;
        float4 gg = g4[c], bb = b4[c], t = vv[i], o;
        o.x = (t.x - mu) * inv * gg.x + bb.x;
        o.y = (t.y - mu) * inv * gg.y + bb.y;
        o.z = (t.z - mu) * inv * gg.z + bb.z;
        o.w = (t.w - mu) * inv * gg.w + bb.w;
        yr[c] = o;
    }
}

// ---------------- fused SiLU(h1)*h2 -> LayerNorm, in place into h1 ----------
__global__ void __launch_bounds__(256) silu_ln_kernel(float* __restrict__ h1,
                                                      const float* __restrict__ h2,
                                                      const float* __restrict__ g,
                                                      const float* __restrict__ b)
{
    constexpr int W = HDIM;
    constexpr int V = W / 1024;  // 4
    __shared__ float red0[8], red1[8];
    __shared__ float stats[2];
    size_t rb = (size_t)blockIdx.x * W;
    const float4* ar = (const float4*)(h1 + rb);
    const float4* cr = (const float4*)(h2 + rb);
    float4 vv[V];
    float s = 0.f, s2 = 0.f;
#pragma unroll
    for (int i = 0; i < V; i++) {
        float4 a = ar[threadIdx.x + i * 256];
        float4 c = cr[threadIdx.x + i * 256];
        float4 t;
        t.x = a.x / (1.f + __expf(-a.x)) * c.x;
        t.y = a.y / (1.f + __expf(-a.y)) * c.y;
        t.z = a.z / (1.f + __expf(-a.z)) * c.z;
        t.w = a.w / (1.f + __expf(-a.w)) * c.w;
        vv[i] = t;
        s  += t.x + t.y + t.z + t.w;
        s2 += t.x*t.x + t.y*t.y + t.z*t.z + t.w*t.w;
    }
#pragma unroll
    for (int o = 16; o; o >>= 1) {
        s  += __shfl_xor_sync(0xffffffffu, s,  o);
        s2 += __shfl_xor_sync(0xffffffffu, s2, o);
    }
    if ((threadIdx.x & 31) == 0) { red0[threadIdx.x >> 5] = s; red1[threadIdx.x >> 5] = s2; }
    __syncthreads();
    if (threadIdx.x == 0) {
        float a = 0.f, c = 0.f;
#pragma unroll
        for (int i = 0; i < 8; i++) { a += red0[i]; c += red1[i]; }
        float mu  = a / (float)W;
        float var = c / (float)W - mu * mu;
        stats[0] = mu;
        stats[1] = rsqrtf(var + LN_EPS);
    }
    __syncthreads();
    float mu = stats[0], inv = stats[1];
    float4* yr = (float4*)(h1 + rb);
    const float4* g4 = (const float4*)g;
    const float4* b4 = (const float4*)b;
#pragma unroll
    for (int i = 0; i < V; i++) {
        int c = threadIdx.x + i * 256;
        float4 gg = g4[c], bb = b4[c], t = vv[i], o;
        o.x = (t.x - mu) * inv * gg.x + bb.x;
        o.y = (t.y - mu) * inv * gg.y + bb.y;
        o.z = (t.z - mu) * inv * gg.z + bb.z;
        o.w = (t.w - mu) * inv * gg.w + bb.w;
        yr[c] = o;
    }
}

// ---------------- RoPE on q,k (skip token 0); scale q by hd^-0.5 ------------
__global__ void __launch_bounds__(256) rope_kernel(float* __restrict__ q,
                                                   float* __restrict__ k,
                                                   const float* __restrict__ cosb,
                                                   const float* __restrict__ sinb)
{
    const float scale = 0.125f;   // 64^-0.5
    int row = blockIdx.x;
    int n = row % NTOK;
    size_t rb = (size_t)row * DMODEL;
    float4* qr = (float4*)(q + rb);
    float4* kr = (float4*)(k + rb);
    int ci = threadIdx.x;                 // float4 index, col = 4*ci
    if (n == 0) {
        float4 t = qr[ci];
        t.x *= scale; t.y *= scale; t.z *= scale; t.w *= scale;
        qr[ci] = t;
        return;
    }
    int d = (ci * 4) & 63;                // position within head, multiple of 4
    const float4 cs = *(const float4*)(cosb + (size_t)(n - 1) * HD + d);
    const float4 sn = *(const float4*)(sinb + (size_t)(n - 1) * HD + d);
    float4 t = qr[ci], o;
    o.x = t.x * cs.x - t.y * sn.x;
    o.y = t.y * cs.y + t.x * sn.y;
    o.z = t.z * cs.z - t.w * sn.z;
    o.w = t.w * cs.w + t.z * sn.w;
    o.x *= scale; o.y *= scale; o.z *= scale; o.w *= scale;
    qr[ci] = o;
    t = kr[ci];
    o.x = t.x * cs.x - t.y * sn.x;
    o.y = t.y * cs.y + t.x * sn.y;
    o.z = t.z * cs.z - t.w * sn.z;
    o.w = t.w * cs.w + t.z * sn.w;
    kr[ci] = o;
}

// ---------------- fused attention: one block per (b,h) ----------------------
// smem: Ks[257*65] Vs[257*65] bias[964] p[8*264] qrow[8*64]
#define ATTN_SMEM_FLOATS (2 * 257 * 65 + 964 + 8 * 264 + 8 * 64)
__global__ void __launch_bounds__(256) attn_kernel(const float* __restrict__ q,
                                                   const float* __restrict__ k,
                                                   const float* __restrict__ v,
                                                   const float* __restrict__ table,
                                                   float* __restrict__ out)
{
    extern __shared__ float sm[];
    float* Ks = sm;
    float* Vs = Ks + 257 * 65;
    float* bs = Vs + 257 * 65;
    float* ps = bs + 964;
    float* qs = ps + 8 * 264;

    int bh = blockIdx.x;
    int b = bh >> 4, h = bh & 15;
    int tid = threadIdx.x, lane = tid & 31, w = tid >> 5;
    size_t base = (size_t)b * NTOK * DMODEL + (size_t)h * HD;

    for (int i = tid; i < NTOK * HD; i += 256) {
        int r = i >> 6, c = i & 63;
        Ks[r * 65 + c] = k[base + (size_t)r * DMODEL + c];
        Vs[r * 65 + c] = v[base + (size_t)r * DMODEL + c];
    }
    for (int i = tid; i < 964; i += 256) bs[i] = table[(size_t)i * NHEAD + h];
    __syncthreads();

    for (int qi = w; qi < NTOK; qi += 8) {
        qs[w * 64 + lane]      = q[base + (size_t)qi * DMODEL + lane];
        qs[w * 64 + lane + 32] = q[base + (size_t)qi * DMODEL + lane + 32];
        __syncwarp();
        int pq = qi - 1, chq = pq >> 4, cwq = pq & 15;
        float e[9];
        float mx = -1e30f;
#pragma unroll
        for (int j = 0; j < 9; j++) {
            int kk = j * 32 + lane;
            float sc = -1e30f;
            if (kk < NTOK) {
                const float* krow = &Ks[kk * 65];
                const float* qrow = &qs[w * 64];
                float dot = 0.f;
#pragma unroll
                for (int d2 = 0; d2 < 64; d2++) dot += qrow[d2] * krow[d2];
                int idx;
                if (qi == 0 && kk == 0)      idx = 963;
                else if (qi == 0)            idx = 961;
                else if (kk == 0)            idx = 962;
                else {
                    int pk = kk - 1;
                    idx = (chq - (pk >> 4) + 15) * 31 + (cwq - (pk & 15) + 15);
                }
                sc = dot + bs[idx];
            }
            e[j] = sc;
            mx = fmaxf(mx, sc);
        }
#pragma unroll
        for (int o = 16; o; o >>= 1) mx = fmaxf(mx, __shfl_xor_sync(0xffffffffu, mx, o));
        float sum = 0.f;
#pragma unroll
        for (int j = 0; j < 9; j++) {
            e[j] = (e[j] > -1e29f) ? __expf(e[j] - mx) : 0.f;
            sum += e[j];
        }
#pragma unroll
        for (int o = 16; o; o >>= 1) sum += __shfl_xor_sync(0xffffffffu, sum, o);
        float inv = 1.f / sum;
        __syncwarp();   // previous iteration's ps reads are done
#pragma unroll
        for (int j = 0; j < 9; j++) {
            int kk = j * 32 + lane;
            if (kk < NTOK) ps[w * 264 + kk] = e[j] * inv;
        }
        __syncwarp();
        float a0 = 0.f, a1 = 0.f;
        const float* pp = &ps[w * 264];
        for (int kk = 0; kk < NTOK; kk++) {
            float pk = pp[kk];
            a0 += pk * Vs[kk * 65 + lane];
            a1 += pk * Vs[kk * 65 + lane + 32];
        }
        out[base + (size_t)qi * DMODEL + lane]      = a0;
        out[base + (size_t)qi * DMODEL + lane + 32] = a1;
    }
}

// ---------------- SGEMM-NT: C[m,n] = sum_k A[m,k]*B[n,k] + bias + res -------
// A: MxK row-major, B: NxK row-major (weight). 128x128x16 tiles, 256 threads.
template<bool RES>
__global__ void __launch_bounds__(256) sgemm_nt(const float* __restrict__ A,
                                                const float* __restrict__ Bw,
                                                const float* __restrict__ bias,
                                                const float* __restrict__ res,
                                                float* __restrict__ C,
                                                int M, int N, int K)
{
    __shared__ float As[16 * 128];
    __shared__ float Bs[16 * 128];
    int tid = threadIdx.x;
    int tx = tid & 15, ty = tid >> 4;
    int n0 = blockIdx.x * 128, m0 = blockIdx.y * 128;

    int lrow = tid >> 2;            // 0..63
    int lk4  = (tid & 3) * 4;       // 0,4,8,12

    float acc[8][8];
#pragma unroll
    for (int i = 0; i < 8; i++)
#pragma unroll
        for (int j = 0; j < 8; j++) acc[i][j] = 0.f;

    for (int k0 = 0; k0 < K; k0 += 16) {
#pragma unroll
        for (int it = 0; it < 2; it++) {
            int row = lrow + it * 64;
            int m = m0 + row;
            float4 av = (m < M) ? *(const float4*)&A[(size_t)m * K + k0 + lk4]
                                : make_float4(0.f, 0.f, 0.f, 0.f);
            As[(lk4 + 0) * 128 + row] = av.x;
            As[(lk4 + 1) * 128 + row] = av.y;
            As[(lk4 + 2) * 128 + row] = av.z;
            As[(lk4 + 3) * 128 + row] = av.w;
            int n = n0 + row;
            float4 bv = *(const float4*)&Bw[(size_t)n * K + k0 + lk4];
            Bs[(lk4 + 0) * 128 + row] = bv.x;
            Bs[(lk4 + 1) * 128 + row] = bv.y;
            Bs[(lk4 + 2) * 128 + row] = bv.z;
            Bs[(lk4 + 3) * 128 + row] = bv.w;
        }
        __syncthreads();
#pragma unroll
        for (int kk = 0; kk < 16; kk++) {
            float4 a0 = *(float4*)&As[kk * 128 + ty * 8];
            float4 a1 = *(float4*)&As[kk * 128 + ty * 8 + 4];
            float4 b0 = *(float4*)&Bs[kk * 128 + tx * 8];
            float4 b1 = *(float4*)&Bs[kk * 128 + tx * 8 + 4];
            float ar[8] = {a0.x, a0.y, a0.z, a0.w, a1.x, a1.y, a1.z, a1.w};
            float br[8] = {b0.x, b0.y, b0.z, b0.w, b1.x, b1.y, b1.z, b1.w};
#pragma unroll
            for (int i = 0; i < 8; i++)
#pragma unroll
                for (int j = 0; j < 8; j++) acc[i][j] += ar[i] * br[j];
        }
        __syncthreads();
    }

    float bj[8];
#pragma unroll
    for (int j = 0; j < 8; j++) bj[j] = bias ? bias[n0 + tx * 8 + j] : 0.f;

#pragma unroll
    for (int i = 0; i < 8; i++) {
        int m = m0 + ty * 8 + i;
        if (m < M) {
            size_t off = (size_t)m * N + n0 + tx * 8;
            float4 o0, o1;
            o0.x = acc[i][0] + bj[0]; o0.y = acc[i][1] + bj[1];
            o0.z = acc[i][2] + bj[2]; o0.w = acc[i][3] + bj[3];
            o1.x = acc[i][4] + bj[4]; o1.y = acc[i][5] + bj[5];
            o1.z = acc[i][6] + bj[6]; o1.w = acc[i][7] + bj[7];
            if (RES) {
                float4 r0 = *(const float4*)&res[off];
                float4 r1 = *(const float4*)&res[off + 4];
                o0.x += r0.x; o0.y += r0.y; o0.z += r0.z; o0.w += r0.w;
                o1.x += r1.x; o1.y += r1.y; o1.z += r1.z; o1.w += r1.w;
            }
            *(float4*)&C[off]     = o0;
            *(float4*)&C[off + 4] = o1;
        }
    }
}

// ---------------- launch --------------------------------------------------
extern "C" void kernel_launch(void* const* d_in, const int* in_sizes, int n_in,
                              void* d_out, int out_size)
{
    const float* x        = (const float*)d_in[0];
    const float* rope_cos = (const float*)d_in[1];
    const float* rope_sin = (const float*)d_in[2];
    const float* q_w      = (const float*)d_in[3];
    const float* q_b      = (const float*)d_in[4];
    const float* k_w      = (const float*)d_in[5];
    const float* v_w      = (const float*)d_in[6];
    const float* v_b      = (const float*)d_in[7];
    const float* table    = (const float*)d_in[8];
    const float* in_g     = (const float*)d_in[9];
    const float* in_b     = (const float*)d_in[10];
    const float* proj_w   = (const float*)d_in[11];
    const float* proj_b   = (const float*)d_in[12];
    const float* n1g      = (const float*)d_in[13];
    const float* n1b      = (const float*)d_in[14];
    const float* n2g      = (const float*)d_in[15];
    const float* n2b      = (const float*)d_in[16];
    const float* w1       = (const float*)d_in[17];
    const float* w1b      = (const float*)d_in[18];
    const float* w2       = (const float*)d_in[19];
    const float* w2b      = (const float*)d_in[20];
    const float* fg       = (const float*)d_in[21];
    const float* fb       = (const float*)d_in[22];
    const float* w3       = (const float*)d_in[23];
    const float* w3b      = (const float*)d_in[24];
    float* out = (float*)d_out;

    float *xn, *q, *k, *v, *att, *x1, *h1, *h2;
    cudaGetSymbolAddress((void**)&xn,  g_xn);
    cudaGetSymbolAddress((void**)&q,   g_q);
    cudaGetSymbolAddress((void**)&k,   g_k);
    cudaGetSymbolAddress((void**)&v,   g_v);
    cudaGetSymbolAddress((void**)&att, g_att);
    cudaGetSymbolAddress((void**)&x1,  g_x1);
    cudaGetSymbolAddress((void**)&h1,  g_h1);
    cudaGetSymbolAddress((void**)&h2,  g_h2);

    int attn_smem = ATTN_SMEM_FLOATS * 4;
    cudaFuncSetAttribute(attn_kernel, cudaFuncAttributeMaxDynamicSharedMemorySize, attn_smem);

    dim3 blk(256);
    dim3 gD((DMODEL + 127) / 128, (T_TOK + 127) / 128);   // (8, 129)
    dim3 gH((HDIM   + 127) / 128, (T_TOK + 127) / 128);   // (32, 129)

    // 1) norm1
    ln_kernel<DMODEL><<<T_TOK, blk>>>(x, n1g, n1b, xn);
    // 2) QKV projections
    sgemm_nt<false><<<gD, blk>>>(xn, q_w, q_b,   nullptr, q, T_TOK, DMODEL, DMODEL);
    sgemm_nt<false><<<gD, blk>>>(xn, k_w, nullptr, nullptr, k, T_TOK, DMODEL, DMODEL);
    sgemm_nt<false><<<gD, blk>>>(xn, v_w, v_b,   nullptr, v, T_TOK, DMODEL, DMODEL);
    // 3) RoPE + q scaling
    rope_kernel<<<T_TOK, blk>>>(q, k, rope_cos, rope_sin);
    // 4) attention
    attn_kernel<<<BATCH * NHEAD, blk, attn_smem>>>(q, k, v, table, att);
    // 5) inner LN, proj (+ residual with original x) -> x1
    ln_kernel<DMODEL><<<T_TOK, blk>>>(att, in_g, in_b, xn);
    sgemm_nt<true><<<gD, blk>>>(xn, proj_w, proj_b, x, x1, T_TOK, DMODEL, DMODEL);
    // 6) norm2
    ln_kernel<DMODEL><<<T_TOK, blk>>>(x1, n2g, n2b, xn);
    // 7) FFN up projections
    sgemm_nt<false><<<gH, blk>>>(xn, w1, w1b, nullptr, h1, T_TOK, HDIM, DMODEL);
    sgemm_nt<false><<<gH, blk>>>(xn, w2, w2b, nullptr, h2, T_TOK, HDIM, DMODEL);
    // 8) silu(h1)*h2 -> ffn LN (in place into h1)
    silu_ln_kernel<<<T_TOK, blk>>>(h1, h2, fg, fb);
    // 9) down projection + residual -> out
    sgemm_nt<true><<<gD, blk>>>(h1, w3, w3b, x1, out, T_TOK, DMODEL, HDIM);
}

// round 3
// speedup vs baseline: 1.6150x; 1.6150x over previous
#include <cuda_runtime.h>
#include <math.h>

#define NTOK   257
#define BATCH  64
#define T_TOK  (BATCH * NTOK)   // 16448
#define DMODEL 1024
#define NHEAD  16
#define HD     64
#define HDIM   4096
#define LN_EPS 1e-5f

// ---------------- scratch (device globals; no allocations allowed) ----------
__device__ float g_xn [(size_t)T_TOK * DMODEL];
__device__ float g_q  [(size_t)T_TOK * DMODEL];
__device__ float g_k  [(size_t)T_TOK * DMODEL];
__device__ float g_v  [(size_t)T_TOK * DMODEL];
__device__ float g_att[(size_t)T_TOK * DMODEL];
__device__ float g_x1 [(size_t)T_TOK * DMODEL];
__device__ float g_h1 [(size_t)T_TOK * HDIM];
__device__ float g_h2 [(size_t)T_TOK * HDIM];

// ---------------- LayerNorm (one row per block, 256 threads) ----------------
template<int W>
__global__ void __launch_bounds__(256) ln_kernel(const float* __restrict__ x,
                                                 const float* __restrict__ g,
                                                 const float* __restrict__ b,
                                                 float* __restrict__ y)
{
    constexpr int V = W / 1024;             // float4s per thread
    __shared__ float red0[8], red1[8];
    __shared__ float stats[2];
    size_t rb = (size_t)blockIdx.x * W;
    const float4* xr = (const float4*)(x + rb);
    float4 vv[V];
    float s = 0.f, s2 = 0.f;
#pragma unroll
    for (int i = 0; i < V; i++) {
        float4 t = xr[threadIdx.x + i * 256];
        vv[i] = t;
        s  += t.x + t.y + t.z + t.w;
        s2 += t.x*t.x + t.y*t.y + t.z*t.z + t.w*t.w;
    }
#pragma unroll
    for (int o = 16; o; o >>= 1) {
        s  += __shfl_xor_sync(0xffffffffu, s,  o);
        s2 += __shfl_xor_sync(0xffffffffu, s2, o);
    }
    if ((threadIdx.x & 31) == 0) { red0[threadIdx.x >> 5] = s; red1[threadIdx.x >> 5] = s2; }
    __syncthreads();
    if (threadIdx.x == 0) {
        float a = 0.f, c = 0.f;
#pragma unroll
        for (int i = 0; i < 8; i++) { a += red0[i]; c += red1[i]; }
        float mu  = a / (float)W;
        float var = c / (float)W - mu * mu;
        stats[0] = mu;
        stats[1] = rsqrtf(var + LN_EPS);
    }
    __syncthreads();
    float mu = stats[0], inv = stats[1];
    float4* yr = (float4*)(y + rb);
    const float4* g4 = (const float4*)g;
    const float4* b4 = (const float4*)b;
#pragma unroll
    for (int i = 0; i < V; i++) {
        int c = threadIdx.x + i * 256;
        float4 gg = g4[c], bb = b4[c], t = vv[i], o;
        o.x = (t.x - mu) * inv * gg.x + bb.x;
        o.y = (t.y - mu) * inv * gg.y + bb.y;
        o.z = (t.z - mu) * inv * gg.z + bb.z;
        o.w = (t.w - mu) * inv * gg.w + bb.w;
        yr[c] = o;
    }
}

// ---------------- fused SiLU(h1)*h2 -> LayerNorm, in place into h1 ----------
__global__ void __launch_bounds__(256) silu_ln_kernel(float* __restrict__ h1,
                                                      const float* __restrict__ h2,
                                                      const float* __restrict__ g,
                                                      const float* __restrict__ b)
{
    constexpr int W = HDIM;
    constexpr int V = W / 1024;  // 4
    __shared__ float red0[8], red1[8];
    __shared__ float stats[2];
    size_t rb = (size_t)blockIdx.x * W;
    const float4* ar = (const float4*)(h1 + rb);
    const float4* cr = (const float4*)(h2 + rb);
    float4 vv[V];
    float s = 0.f, s2 = 0.f;
#pragma unroll
    for (int i = 0; i < V; i++) {
        float4 a = ar[threadIdx.x + i * 256];
        float4 c = cr[threadIdx.x + i * 256];
        float4 t;
        t.x = a.x / (1.f + __expf(-a.x)) * c.x;
        t.y = a.y / (1.f + __expf(-a.y)) * c.y;
        t.z = a.z / (1.f + __expf(-a.z)) * c.z;
        t.w = a.w / (1.f + __expf(-a.w)) * c.w;
        vv[i] = t;
        s  += t.x + t.y + t.z + t.w;
        s2 += t.x*t.x + t.y*t.y + t.z*t.z + t.w*t.w;
    }
#pragma unroll
    for (int o = 16; o; o >>= 1) {
        s  += __shfl_xor_sync(0xffffffffu, s,  o);
        s2 += __shfl_xor_sync(0xffffffffu, s2, o);
    }
    if ((threadIdx.x & 31) == 0) { red0[threadIdx.x >> 5] = s; red1[threadIdx.x >> 5] = s2; }
    __syncthreads();
    if (threadIdx.x == 0) {
        float a = 0.f, c = 0.f;
#pragma unroll
        for (int i = 0; i < 8; i++) { a += red0[i]; c += red1[i]; }
        float mu  = a / (float)W;
        float var = c / (float)W - mu * mu;
        stats[0] = mu;
        stats[1] = rsqrtf(var + LN_EPS);
    }
    __syncthreads();
    float mu = stats[0], inv = stats[1];
    float4* yr = (float4*)(h1 + rb);
    const float4* g4 = (const float4*)g;
    const float4* b4 = (const float4*)b;
#pragma unroll
    for (int i = 0; i < V; i++) {
        int c = threadIdx.x + i * 256;
        float4 gg = g4[c], bb = b4[c], t = vv[i], o;
        o.x = (t.x - mu) * inv * gg.x + bb.x;
        o.y = (t.y - mu) * inv * gg.y + bb.y;
        o.z = (t.z - mu) * inv * gg.z + bb.z;
        o.w = (t.w - mu) * inv * gg.w + bb.w;
        yr[c] = o;
    }
}

// ---------------- RoPE on q,k (skip token 0); scale q by hd^-0.5 ------------
__global__ void __launch_bounds__(256) rope_kernel(float* __restrict__ q,
                                                   float* __restrict__ k,
                                                   const float* __restrict__ cosb,
                                                   const float* __restrict__ sinb)
{
    const float scale = 0.125f;   // 64^-0.5
    int row = blockIdx.x;
    int n = row % NTOK;
    size_t rb = (size_t)row * DMODEL;
    float4* qr = (float4*)(q + rb);
    float4* kr = (float4*)(k + rb);
    int ci = threadIdx.x;                 // float4 index, col = 4*ci
    if (n == 0) {
        float4 t = qr[ci];
        t.x *= scale; t.y *= scale; t.z *= scale; t.w *= scale;
        qr[ci] = t;
        return;
    }
    int d = (ci * 4) & 63;                // position within head, multiple of 4
    const float4 cs = *(const float4*)(cosb + (size_t)(n - 1) * HD + d);
    const float4 sn = *(const float4*)(sinb + (size_t)(n - 1) * HD + d);
    float4 t = qr[ci], o;
    o.x = t.x * cs.x - t.y * sn.x;
    o.y = t.y * cs.y + t.x * sn.y;
    o.z = t.z * cs.z - t.w * sn.z;
    o.w = t.w * cs.w + t.z * sn.w;
    o.x *= scale; o.y *= scale; o.z *= scale; o.w *= scale;
    qr[ci] = o;
    t = kr[ci];
    o.x = t.x * cs.x - t.y * sn.x;
    o.y = t.y * cs.y + t.x * sn.y;
    o.z = t.z * cs.z - t.w * sn.z;
    o.w = t.w * cs.w + t.z * sn.w;
    kr[ci] = o;
}

// ---------------- fused attention: one block per (b,h) ----------------------
// smem: Ks[257*65] Vs[257*65] bias[964] p[8*264] qrow[8*64]
#define ATTN_SMEM_FLOATS (2 * 257 * 65 + 964 + 8 * 264 + 8 * 64)
__global__ void __launch_bounds__(256) attn_kernel(const float* __restrict__ q,
                                                   const float* __restrict__ k,
                                                   const float* __restrict__ v,
                                                   const float* __restrict__ table,
                                                   float* __restrict__ out)
{
    extern __shared__ float sm[];
    float* Ks = sm;
    float* Vs = Ks + 257 * 65;
    float* bs = Vs + 257 * 65;
    float* ps = bs + 964;
    float* qs = ps + 8 * 264;

    int bh = blockIdx.x;
    int b = bh >> 4, h = bh & 15;
    int tid = threadIdx.x, lane = tid & 31, w = tid >> 5;
    size_t base = (size_t)b * NTOK * DMODEL + (size_t)h * HD;

    for (int i = tid; i < NTOK * HD; i += 256) {
        int r = i >> 6, c = i & 63;
        Ks[r * 65 + c] = k[base + (size_t)r * DMODEL + c];
        Vs[r * 65 + c] = v[base + (size_t)r * DMODEL + c];
    }
    for (int i = tid; i < 964; i += 256) bs[i] = table[(size_t)i * NHEAD + h];
    __syncthreads();

    for (int qi = w; qi < NTOK; qi += 8) {
        qs[w * 64 + lane]      = q[base + (size_t)qi * DMODEL + lane];
        qs[w * 64 + lane + 32] = q[base + (size_t)qi * DMODEL + lane + 32];
        __syncwarp();
        int pq = qi - 1, chq = pq >> 4, cwq = pq & 15;
        float e[9];
        float mx = -1e30f;
#pragma unroll
        for (int j = 0; j < 9; j++) {
            int kk = j * 32 + lane;
            float sc = -1e30f;
            if (kk < NTOK) {
                const float* krow = &Ks[kk * 65];
                const float* qrow = &qs[w * 64];
                float dot = 0.f;
#pragma unroll
                for (int d2 = 0; d2 < 64; d2++) dot += qrow[d2] * krow[d2];
                int idx;
                if (qi == 0 && kk == 0)      idx = 963;
                else if (qi == 0)            idx = 961;
                else if (kk == 0)            idx = 962;
                else {
                    int pk = kk - 1;
                    idx = (chq - (pk >> 4) + 15) * 31 + (cwq - (pk & 15) + 15);
                }
                sc = dot + bs[idx];
            }
            e[j] = sc;
            mx = fmaxf(mx, sc);
        }
#pragma unroll
        for (int o = 16; o; o >>= 1) mx = fmaxf(mx, __shfl_xor_sync(0xffffffffu, mx, o));
        float sum = 0.f;
#pragma unroll
        for (int j = 0; j < 9; j++) {
            e[j] = (e[j] > -1e29f) ? __expf(e[j] - mx) : 0.f;
            sum += e[j];
        }
#pragma unroll
        for (int o = 16; o; o >>= 1) sum += __shfl_xor_sync(0xffffffffu, sum, o);
        float inv = 1.f / sum;
        __syncwarp();   // previous iteration's ps reads are done
#pragma unroll
        for (int j = 0; j < 9; j++) {
            int kk = j * 32 + lane;
            if (kk < NTOK) ps[w * 264 + kk] = e[j] * inv;
        }
        __syncwarp();
        float a0 = 0.f, a1 = 0.f;
        const float* pp = &ps[w * 264];
        for (int kk = 0; kk < NTOK; kk++) {
            float pk = pp[kk];
            a0 += pk * Vs[kk * 65 + lane];
            a1 += pk * Vs[kk * 65 + lane + 32];
        }
        out[base + (size_t)qi * DMODEL + lane]      = a0;
        out[base + (size_t)qi * DMODEL + lane + 32] = a1;
    }
}

// ---------------- SGEMM-NT: C[m,n] = sum_k A[m,k]*B[n,k] + bias + res -------
// A: MxK row-major, B: NxK row-major (weight). 128x128x16 tiles, 256 threads.
template<bool RES>
__global__ void __launch_bounds__(256) sgemm_nt(const float* __restrict__ A,
                                                const float* __restrict__ Bw,
                                                const float* __restrict__ bias,
                                                const float* __restrict__ res,
                                                float* __restrict__ C,
                                                int M, int N, int K)
{
    __shared__ float As[16 * 128];
    __shared__ float Bs[16 * 128];
    int tid = threadIdx.x;
    int tx = tid & 15, ty = tid >> 4;
    int n0 = blockIdx.x * 128, m0 = blockIdx.y * 128;

    int lrow = tid >> 2;            // 0..63
    int lk4  = (tid & 3) * 4;       // 0,4,8,12

    float acc[8][8];
#pragma unroll
    for (int i = 0; i < 8; i++)
#pragma unroll
        for (int j = 0; j < 8; j++) acc[i][j] = 0.f;

    for (int k0 = 0; k0 < K; k0 += 16) {
#pragma unroll
        for (int it = 0; it < 2; it++) {
            int row = lrow + it * 64;
            int m = m0 + row;
            float4 av = (m < M) ? *(const float4*)&A[(size_t)m * K + k0 + lk4]
                                : make_float4(0.f, 0.f, 0.f, 0.f);
            As[(lk4 + 0) * 128 + row] = av.x;
            As[(lk4 + 1) * 128 + row] = av.y;
            As[(lk4 + 2) * 128 + row] = av.z;
            As[(lk4 + 3) * 128 + row] = av.w;
            int n = n0 + row;
            float4 bv = *(const float4*)&Bw[(size_t)n * K + k0 + lk4];
            Bs[(lk4 + 0) * 128 + row] = bv.x;
            Bs[(lk4 + 1) * 128 + row] = bv.y;
            Bs[(lk4 + 2) * 128 + row] = bv.z;
            Bs[(lk4 + 3) * 128 + row] = bv.w;
        }
        __syncthreads();
#pragma unroll
        for (int kk = 0; kk < 16; kk++) {
            float4 a0 = *(float4*)&As[kk * 128 + ty * 8];
            float4 a1 = *(float4*)&As[kk * 128 + ty * 8 + 4];
            float4 b0 = *(float4*)&Bs[kk * 128 + tx * 8];
            float4 b1 = *(float4*)&Bs[kk * 128 + tx * 8 + 4];
            float ar[8] = {a0.x, a0.y, a0.z, a0.w, a1.x, a1.y, a1.z, a1.w};
            float br[8] = {b0.x, b0.y, b0.z, b0.w, b1.x, b1.y, b1.z, b1.w};
#pragma unroll
            for (int i = 0; i < 8; i++)
#pragma unroll
                for (int j = 0; j < 8; j++) acc[i][j] += ar[i] * br[j];
        }
        __syncthreads();
    }

    float bj[8];
#pragma unroll
    for (int j = 0; j < 8; j++) bj[j] = bias ? bias[n0 + tx * 8 + j] : 0.f;

#pragma unroll
    for (int i = 0; i < 8; i++) {
        int m = m0 + ty * 8 + i;
        if (m < M) {
            size_t off = (size_t)m * N + n0 + tx * 8;
            float4 o0, o1;
            o0.x = acc[i][0] + bj[0]; o0.y = acc[i][1] + bj[1];
            o0.z = acc[i][2] + bj[2]; o0.w = acc[i][3] + bj[3];
            o1.x = acc[i][4] + bj[4]; o1.y = acc[i][5] + bj[5];
            o1.z = acc[i][6] + bj[6]; o1.w = acc[i][7] + bj[7];
            if (RES) {
                float4 r0 = *(const float4*)&res[off];
                float4 r1 = *(const float4*)&res[off + 4];
                o0.x += r0.x; o0.y += r0.y; o0.z += r0.z; o0.w += r0.w;
                o1.x += r1.x; o1.y += r1.y; o1.z += r1.z; o1.w += r1.w;
            }
            *(float4*)&C[off]     = o0;
            *(float4*)&C[off + 4] = o1;
        }
    }
}

// ---------------- launch --------------------------------------------------
extern "C" void kernel_launch(void* const* d_in, const int* in_sizes, int n_in,
                              void* d_out, int out_size)
{
    const float* x        = (const float*)d_in[0];
    const float* rope_cos = (const float*)d_in[1];
    const float* rope_sin = (const float*)d_in[2];
    const float* q_w      = (const float*)d_in[3];
    const float* q_b      = (const float*)d_in[4];
    const float* k_w      = (const float*)d_in[5];
    const float* v_w      = (const float*)d_in[6];
    const float* v_b      = (const float*)d_in[7];
    const float* table    = (const float*)d_in[8];
    const float* in_g     = (const float*)d_in[9];
    const float* in_b     = (const float*)d_in[10];
    const float* proj_w   = (const float*)d_in[11];
    const float* proj_b   = (const float*)d_in[12];
    const float* n1g      = (const float*)d_in[13];
    const float* n1b      = (const float*)d_in[14];
    const float* n2g      = (const float*)d_in[15];
    const float* n2b      = (const float*)d_in[16];
    const float* w1       = (const float*)d_in[17];
    const float* w1b      = (const float*)d_in[18];
    const float* w2       = (const float*)d_in[19];
    const float* w2b      = (const float*)d_in[20];
    const float* fg       = (const float*)d_in[21];
    const float* fb       = (const float*)d_in[22];
    const float* w3       = (const float*)d_in[23];
    const float* w3b      = (const float*)d_in[24];
    float* out = (float*)d_out;

    float *xn, *q, *k, *v, *att, *x1, *h1, *h2;
    cudaGetSymbolAddress((void**)&xn,  g_xn);
    cudaGetSymbolAddress((void**)&q,   g_q);
    cudaGetSymbolAddress((void**)&k,   g_k);
    cudaGetSymbolAddress((void**)&v,   g_v);
    cudaGetSymbolAddress((void**)&att, g_att);
    cudaGetSymbolAddress((void**)&x1,  g_x1);
    cudaGetSymbolAddress((void**)&h1,  g_h1);
    cudaGetSymbolAddress((void**)&h2,  g_h2);

    int attn_smem = ATTN_SMEM_FLOATS * 4;
    cudaFuncSetAttribute(attn_kernel, cudaFuncAttributeMaxDynamicSharedMemorySize, attn_smem);

    dim3 blk(256);
    dim3 gD((DMODEL + 127) / 128, (T_TOK + 127) / 128);   // (8, 129)
    dim3 gH((HDIM   + 127) / 128, (T_TOK + 127) / 128);   // (32, 129)

    // 1) norm1
    ln_kernel<DMODEL><<<T_TOK, blk>>>(x, n1g, n1b, xn);
    // 2) QKV projections
    sgemm_nt<false><<<gD, blk>>>(xn, q_w, q_b,   nullptr, q, T_TOK, DMODEL, DMODEL);
    sgemm_nt<false><<<gD, blk>>>(xn, k_w, nullptr, nullptr, k, T_TOK, DMODEL, DMODEL);
    sgemm_nt<false><<<gD, blk>>>(xn, v_w, v_b,   nullptr, v, T_TOK, DMODEL, DMODEL);
    // 3) RoPE + q scaling
    rope_kernel<<<T_TOK, blk>>>(q, k, rope_cos, rope_sin);
    // 4) attention
    attn_kernel<<<BATCH * NHEAD, blk, attn_smem>>>(q, k, v, table, att);
    // 5) inner LN, proj (+ residual with original x) -> x1
    ln_kernel<DMODEL><<<T_TOK, blk>>>(att, in_g, in_b, xn);
    sgemm_nt<true><<<gD, blk>>>(xn, proj_w, proj_b, x, x1, T_TOK, DMODEL, DMODEL);
    // 6) norm2
    ln_kernel<DMODEL><<<T_TOK, blk>>>(x1, n2g, n2b, xn);
    // 7) FFN up projections
    sgemm_nt<false><<<gH, blk>>>(xn, w1, w1b, nullptr, h1, T_TOK, HDIM, DMODEL);
    sgemm_nt<false><<<gH, blk>>>(xn, w2, w2b, nullptr, h2, T_TOK, HDIM, DMODEL);
    // 8) silu(h1)*h2 -> ffn LN (in place into h1)
    silu_ln_kernel<<<T_TOK, blk>>>(h1, h2, fg, fb);
    // 9) down projection + residual -> out
    sgemm_nt<true><<<gD, blk>>>(h1, w3, w3b, x1, out, T_TOK, DMODEL, HDIM);
}